// round 11
// baseline (speedup 1.0000x reference)
#include <cuda_runtime.h>
#include <cuda_fp16.h>
#include <cstdint>

#define BATCH 256
#define N_GENES 8192
#define WM 4
#define HID (N_GENES * WM)       // 32768
#define N_TF 1024
#define GPT 64
#define EDGES3 (GPT * WM)        // 256
#define EPS 1e-5f
#define GENES_PER_BLOCK 8

// Scratch: layer-2 output stored TRANSPOSED in fp16: hT[col * BATCH + b]
__device__ __half g_hT[HID * BATCH];

typedef unsigned long long u64;

// ---- packed fp32x2 ops (Blackwell sm_103a) ----
__device__ __forceinline__ u64 pk2(float lo, float hi) {
    u64 r; asm("mov.b64 %0, {%1, %2};" : "=l"(r) : "f"(lo), "f"(hi)); return r;
}
__device__ __forceinline__ void upk2(u64 v, float& lo, float& hi) {
    asm("mov.b64 {%0, %1}, %2;" : "=f"(lo), "=f"(hi) : "l"(v));
}
__device__ __forceinline__ u64 fma2(u64 a, u64 b, u64 c) {
    u64 d; asm("fma.rn.f32x2 %0, %1, %2, %3;" : "=l"(d) : "l"(a), "l"(b), "l"(c)); return d;
}
__device__ __forceinline__ u64 add2(u64 a, u64 b) {
    u64 d; asm("add.rn.f32x2 %0, %1, %2;" : "=l"(d) : "l"(a), "l"(b)); return d;
}
__device__ __forceinline__ u64 mul2(u64 a, u64 b) {
    u64 d; asm("mul.rn.f32x2 %0, %1, %2;" : "=l"(d) : "l"(a), "l"(b)); return d;
}
__device__ __forceinline__ u64 relu2(u64 a) {
    float x, y; upk2(a, x, y);
    return pk2(fmaxf(x, 0.f), fmaxf(y, 0.f));
}

struct __align__(8) H22 { __half2 a, b; };

// Warp-local BN stats for 4 columns via smem transpose reduction.
// sbnw: per-warp float[8*33] slab. Inputs sv[j], qv[j] = this lane's partial
// sum / sumsq for column j over its 8 batch elements.
// Outputs m[j], inv[j] broadcast to all lanes.
__device__ __forceinline__ void bn_stats4(float* sbnw, int lane,
                                          const float sv[4], const float qv[4],
                                          float m[4], float inv[4]) {
#pragma unroll
    for (int v = 0; v < 4; v++) {
        sbnw[v * 33 + lane]       = sv[v];
        sbnw[(v + 4) * 33 + lane] = qv[v];
    }
    __syncwarp();
    const int v = lane & 7, gsrc = (lane >> 3) * 8;
    float tot = 0.f;
#pragma unroll
    for (int k = 0; k < 8; k++)
        tot += sbnw[v * 33 + gsrc + k];
    tot += __shfl_xor_sync(0xffffffffu, tot, 8);
    tot += __shfl_xor_sync(0xffffffffu, tot, 16);
    // lane j holds sum_j total; lane 4+j holds sumsq_j total (replicated /8)
#pragma unroll
    for (int j = 0; j < 4; j++) {
        float s = __shfl_sync(0xffffffffu, tot, j);
        float q = __shfl_sync(0xffffffffu, tot, 4 + j);
        float mm = s * (1.0f / BATCH);
        float vv = fmaxf(q * (1.0f / BATCH) - mm * mm, 0.0f);
        m[j] = mm;
        inv[j] = rsqrtf(vv + EPS);
    }
    __syncwarp();   // slab safe for reuse
}

// Fused: layer1 -> relu -> BN -> layer2 -> relu -> BN. One warp per gene.
// Lane owns batches {4L..4L+3} and {128+4L..128+4L+3} as f32x2 pairs.
__global__ __launch_bounds__(256) void k_layers12(
    const float* __restrict__ x,    // [BATCH, N_GENES] row-major
    const float* __restrict__ w1, const float* __restrict__ b1,
    const float* __restrict__ w2, const float* __restrict__ b2)
{
    __shared__ float sxT[GENES_PER_BLOCK][260];
    __shared__ float sbn[8][8 * 33];

    const int g0 = blockIdx.x * GENES_PER_BLOCK;
    const int t = threadIdx.x;
    const int warp = t >> 5;
    const int lane = t & 31;

    // Tile load: thread t = batch row t, 8 genes via 2x LDG.128.
    {
        const float4* xr = reinterpret_cast<const float4*>(x + (size_t)t * N_GENES + g0);
        float4 a = xr[0], b = xr[1];
        sxT[0][t] = a.x; sxT[1][t] = a.y; sxT[2][t] = a.z; sxT[3][t] = a.w;
        sxT[4][t] = b.x; sxT[5][t] = b.y; sxT[6][t] = b.z; sxT[7][t] = b.w;
    }
    __syncthreads();

    const int gi = warp;
    const int g = g0 + gi;

    // x pairs: [k][pp]
    u64 xp[2][2];
#pragma unroll
    for (int k = 0; k < 2; k++) {
        float4 xv = *reinterpret_cast<const float4*>(&sxT[gi][128 * k + 4 * lane]);
        xp[k][0] = pk2(xv.x, xv.y);
        xp[k][1] = pk2(xv.z, xv.w);
    }

    // Vectorized weight loads
    float4 w1q = *reinterpret_cast<const float4*>(w1 + 4 * g);
    float4 b1q = *reinterpret_cast<const float4*>(b1 + 4 * g);
    float4 b2q = *reinterpret_cast<const float4*>(b2 + 4 * g);
    float4 w2q0 = *reinterpret_cast<const float4*>(w2 + 16 * g);
    float4 w2q1 = *reinterpret_cast<const float4*>(w2 + 16 * g + 4);
    float4 w2q2 = *reinterpret_cast<const float4*>(w2 + 16 * g + 8);
    float4 w2q3 = *reinterpret_cast<const float4*>(w2 + 16 * g + 12);
    float w1v[4] = {w1q.x, w1q.y, w1q.z, w1q.w};
    float b1v[4] = {b1q.x, b1q.y, b1q.z, b1q.w};
    float b2v[4] = {b2q.x, b2q.y, b2q.z, b2q.w};
    float w2v[16] = {w2q0.x, w2q0.y, w2q0.z, w2q0.w,
                     w2q1.x, w2q1.y, w2q1.z, w2q1.w,
                     w2q2.x, w2q2.y, w2q2.z, w2q2.w,
                     w2q3.x, w2q3.y, w2q3.z, w2q3.w};

    u64 w1p[4], b1p[4];
#pragma unroll
    for (int j = 0; j < 4; j++) {
        w1p[j] = pk2(w1v[j], w1v[j]);
        b1p[j] = pk2(b1v[j], b1v[j]);
    }

    // layer1 + relu (raw, pre-BN), packed pairs: h1[k][pp][j]
    u64 h1[2][2][4];
#pragma unroll
    for (int k = 0; k < 2; k++)
#pragma unroll
        for (int pp = 0; pp < 2; pp++)
#pragma unroll
            for (int j = 0; j < 4; j++)
                h1[k][pp][j] = relu2(fma2(w1p[j], xp[k][pp], b1p[j]));

    // BN1 stats (smem transpose reduction), fold into layer2 weights
    float sv[4], qv[4];
#pragma unroll
    for (int j = 0; j < 4; j++) {
        u64 sp = add2(add2(h1[0][0][j], h1[0][1][j]), add2(h1[1][0][j], h1[1][1][j]));
        u64 qp = mul2(h1[0][0][j], h1[0][0][j]);
        qp = fma2(h1[0][1][j], h1[0][1][j], qp);
        qp = fma2(h1[1][0][j], h1[1][0][j], qp);
        qp = fma2(h1[1][1][j], h1[1][1][j], qp);
        float ax, ay;
        upk2(sp, ax, ay); sv[j] = ax + ay;
        upk2(qp, ax, ay); qv[j] = ax + ay;
    }
    float m1[4], inv1[4];
    bn_stats4(sbn[warp], lane, sv, qv, m1, inv1);

    u64 w2p[16], b2p[4];
#pragma unroll
    for (int i = 0; i < 4; i++) {
        float bb = b2v[i];
#pragma unroll
        for (int j = 0; j < 4; j++) {
            float wf = w2v[4 * i + j] * inv1[j];
            w2p[4 * i + j] = pk2(wf, wf);
            bb -= wf * m1[j];
        }
        b2p[i] = pk2(bb, bb);
    }

    // layer2 + relu, packed: h2[k][pp][i]
    u64 h2[2][2][4];
#pragma unroll
    for (int k = 0; k < 2; k++)
#pragma unroll
        for (int pp = 0; pp < 2; pp++)
#pragma unroll
            for (int i = 0; i < 4; i++) {
                u64 acc = b2p[i];
#pragma unroll
                for (int j = 0; j < 4; j++) acc = fma2(w2p[4 * i + j], h1[k][pp][j], acc);
                h2[k][pp][i] = relu2(acc);
            }

    // BN2 stats
#pragma unroll
    for (int i = 0; i < 4; i++) {
        u64 sp = add2(add2(h2[0][0][i], h2[0][1][i]), add2(h2[1][0][i], h2[1][1][i]));
        u64 qp = mul2(h2[0][0][i], h2[0][0][i]);
        qp = fma2(h2[0][1][i], h2[0][1][i], qp);
        qp = fma2(h2[1][0][i], h2[1][0][i], qp);
        qp = fma2(h2[1][1][i], h2[1][1][i], qp);
        float ax, ay;
        upk2(sp, ax, ay); sv[i] = ax + ay;
        upk2(qp, ax, ay); qv[i] = ax + ay;
    }
    float m2[4], inv2s[4];
    bn_stats4(sbn[warp], lane, sv, qv, m2, inv2s);

    // Normalize packed, transposed ST.64 half2 store
#pragma unroll
    for (int i = 0; i < 4; i++) {
        u64 inv2 = pk2(inv2s[i], inv2s[i]);
        u64 sh2  = pk2(-m2[i] * inv2s[i], -m2[i] * inv2s[i]);
        __half2* dst = reinterpret_cast<__half2*>(&g_hT[(4 * g + i) * BATCH]);
#pragma unroll
        for (int k = 0; k < 2; k++) {
            u64 p0 = fma2(h2[k][0][i], inv2, sh2);
            u64 p1 = fma2(h2[k][1][i], inv2, sh2);
            float a0, a1, a2, a3;
            upk2(p0, a0, a1); upk2(p1, a2, a3);
            H22 hv;
            hv.a = __floats2half2_rn(a0, a1);
            hv.b = __floats2half2_rn(a2, a3);
            *reinterpret_cast<H22*>(&dst[64 * k + 2 * lane]) = hv;
        }
    }
}

// layer3 (R7 config — best measured): one block (8 warps) per TF; warp handles
// 32 edges in 8 chunks of 4 staged LDG.128s. fp32 accumulation. b3 omitted —
// a per-column constant cancels exactly through the final BatchNorm.
struct __align__(8) WC { float w; int boff; };

__device__ __forceinline__ void fma8(float* acc, float w, const uint4& v) {
    float2 f0 = __half22float2(*reinterpret_cast<const __half2*>(&v.x));
    float2 f1 = __half22float2(*reinterpret_cast<const __half2*>(&v.y));
    float2 f2 = __half22float2(*reinterpret_cast<const __half2*>(&v.z));
    float2 f3 = __half22float2(*reinterpret_cast<const __half2*>(&v.w));
    acc[0] = fmaf(w, f0.x, acc[0]);
    acc[1] = fmaf(w, f0.y, acc[1]);
    acc[2] = fmaf(w, f1.x, acc[2]);
    acc[3] = fmaf(w, f1.y, acc[3]);
    acc[4] = fmaf(w, f2.x, acc[4]);
    acc[5] = fmaf(w, f2.y, acc[5]);
    acc[6] = fmaf(w, f3.x, acc[6]);
    acc[7] = fmaf(w, f3.y, acc[7]);
}

__device__ __forceinline__ float2 warp_sum2(float2 v) {
#pragma unroll
    for (int o = 16; o; o >>= 1) {
        v.x += __shfl_xor_sync(0xffffffffu, v.x, o);
        v.y += __shfl_xor_sync(0xffffffffu, v.y, o);
    }
    return v;
}

__global__ __launch_bounds__(256) void k_layer3(
    const float* __restrict__ w3,
    const int* __restrict__ cols3,
    float* __restrict__ out)   // [BATCH, N_TF]
{
    const int tf = blockIdx.x;
    const int t = threadIdx.x;        // 0..255
    const int warp = t >> 5;
    const int lane = t & 31;

    __shared__ WC swc[EDGES3];
    __shared__ float sacc[8][BATCH];      // 8 KB
    __shared__ float2 sred[8];

    swc[t].w    = w3[tf * EDGES3 + t];
    swc[t].boff = cols3[tf * EDGES3 + t] * (BATCH * 2);   // bytes
    __syncthreads();

    const char* hbase = reinterpret_cast<const char*>(g_hT) + lane * 16;
    const int ebase = warp * 32;

    float acc[8];
#pragma unroll
    for (int s = 0; s < 8; s++) acc[s] = 0.f;

#pragma unroll
    for (int c = 0; c < 8; c++) {
        WC a0 = swc[ebase + 4 * c + 0];
        WC a1 = swc[ebase + 4 * c + 1];
        WC a2 = swc[ebase + 4 * c + 2];
        WC a3 = swc[ebase + 4 * c + 3];
        uint4 v0 = *reinterpret_cast<const uint4*>(hbase + a0.boff);
        uint4 v1 = *reinterpret_cast<const uint4*>(hbase + a1.boff);
        uint4 v2 = *reinterpret_cast<const uint4*>(hbase + a2.boff);
        uint4 v3 = *reinterpret_cast<const uint4*>(hbase + a3.boff);
        fma8(acc, a0.w, v0);
        fma8(acc, a1.w, v1);
        fma8(acc, a2.w, v2);
        fma8(acc, a3.w, v3);
    }

    // Park partials: warp's acc[s] is batch 8*lane+s
    *reinterpret_cast<float4*>(&sacc[warp][8 * lane])     = make_float4(acc[0], acc[1], acc[2], acc[3]);
    *reinterpret_cast<float4*>(&sacc[warp][8 * lane + 4]) = make_float4(acc[4], acc[5], acc[6], acc[7]);
    __syncthreads();

    // Thread t owns batch b = t: sum over the 8 warps' partials.
    float z = 0.f;
#pragma unroll
    for (int w = 0; w < 8; w++) z += sacc[w][t];

    // Single-pass BN over the 256 batch values.
    float2 ss = warp_sum2(make_float2(z, z * z));
    if (lane == 0) sred[warp] = ss;
    __syncthreads();
    float S = 0.f, S2 = 0.f;
#pragma unroll
    for (int i = 0; i < 8; i++) { S += sred[i].x; S2 += sred[i].y; }
    float m = S * (1.0f / BATCH);
    float var = fmaxf(S2 * (1.0f / BATCH) - m * m, 0.0f);
    float inv = rsqrtf(var + EPS);

    out[t * N_TF + tf] = (z - m) * inv;
}

extern "C" void kernel_launch(void* const* d_in, const int* in_sizes, int n_in,
                              void* d_out, int out_size)
{
    const float* x  = (const float*)d_in[0];
    const float* w1 = (const float*)d_in[1];
    const float* b1 = (const float*)d_in[2];
    const float* w2 = (const float*)d_in[3];
    const float* b2 = (const float*)d_in[4];
    const float* w3 = (const float*)d_in[5];
    const int* cols3 = (const int*)d_in[12];
    float* out = (float*)d_out;

    k_layers12<<<N_GENES / GENES_PER_BLOCK, 256>>>(x, w1, b1, w2, b2);
    k_layer3<<<N_TF, 256>>>(w3, cols3, out);
}

// round 12
// speedup vs baseline: 1.0714x; 1.0714x over previous
#include <cuda_runtime.h>
#include <cuda_fp16.h>
#include <cstdint>

#define BATCH 256
#define N_GENES 8192
#define WM 4
#define HID (N_GENES * WM)       // 32768
#define N_TF 1024
#define GPT 64
#define EDGES3 (GPT * WM)        // 256
#define EPS 1e-5f
#define GENES_PER_BLOCK 8

// Scratch: layer-2 output stored TRANSPOSED in fp16: hT[col * BATCH + b]
__device__ __half g_hT[HID * BATCH];

typedef unsigned long long u64;

// ---- packed fp32x2 ops (Blackwell sm_103a) ----
__device__ __forceinline__ u64 pk2(float lo, float hi) {
    u64 r; asm("mov.b64 %0, {%1, %2};" : "=l"(r) : "f"(lo), "f"(hi)); return r;
}
__device__ __forceinline__ void upk2(u64 v, float& lo, float& hi) {
    asm("mov.b64 {%0, %1}, %2;" : "=f"(lo), "=f"(hi) : "l"(v));
}
__device__ __forceinline__ u64 fma2(u64 a, u64 b, u64 c) {
    u64 d; asm("fma.rn.f32x2 %0, %1, %2, %3;" : "=l"(d) : "l"(a), "l"(b), "l"(c)); return d;
}
__device__ __forceinline__ u64 add2(u64 a, u64 b) {
    u64 d; asm("add.rn.f32x2 %0, %1, %2;" : "=l"(d) : "l"(a), "l"(b)); return d;
}
__device__ __forceinline__ u64 mul2(u64 a, u64 b) {
    u64 d; asm("mul.rn.f32x2 %0, %1, %2;" : "=l"(d) : "l"(a), "l"(b)); return d;
}
__device__ __forceinline__ u64 relu2(u64 a) {
    float x, y; upk2(a, x, y);
    return pk2(fmaxf(x, 0.f), fmaxf(y, 0.f));
}

__device__ __forceinline__ float2 warp_sum2(float2 v) {
#pragma unroll
    for (int o = 16; o; o >>= 1) {
        v.x += __shfl_xor_sync(0xffffffffu, v.x, o);
        v.y += __shfl_xor_sync(0xffffffffu, v.y, o);
    }
    return v;
}

struct __align__(8) H22 { __half2 a, b; };

// Fused: layer1 -> relu -> BN -> layer2 -> relu -> BN. One warp per gene.
// Lane owns batches {4L..4L+3} and {128+4L..128+4L+3} as f32x2 pairs.
// min-blocks=4 caps regs at 64 -> 50% occupancy (was ~25% at 100+ regs).
__global__ __launch_bounds__(256, 4) void k_layers12(
    const float* __restrict__ x,    // [BATCH, N_GENES] row-major
    const float* __restrict__ w1, const float* __restrict__ b1,
    const float* __restrict__ w2, const float* __restrict__ b2)
{
    __shared__ float sxT[GENES_PER_BLOCK][260];

    const int g0 = blockIdx.x * GENES_PER_BLOCK;
    const int t = threadIdx.x;
    const int warp = t >> 5;
    const int lane = t & 31;

    // Tile load: thread t = batch row t, 8 genes via 2x LDG.128.
    {
        const float4* xr = reinterpret_cast<const float4*>(x + (size_t)t * N_GENES + g0);
        float4 a = xr[0], b = xr[1];
        sxT[0][t] = a.x; sxT[1][t] = a.y; sxT[2][t] = a.z; sxT[3][t] = a.w;
        sxT[4][t] = b.x; sxT[5][t] = b.y; sxT[6][t] = b.z; sxT[7][t] = b.w;
    }
    __syncthreads();

    const int gi = warp;
    const int g = g0 + gi;

    // x pairs: [k][pp]
    u64 xp[2][2];
#pragma unroll
    for (int k = 0; k < 2; k++) {
        float4 xv = *reinterpret_cast<const float4*>(&sxT[gi][128 * k + 4 * lane]);
        xp[k][0] = pk2(xv.x, xv.y);
        xp[k][1] = pk2(xv.z, xv.w);
    }

    // Vectorized weight loads
    float4 w1q = *reinterpret_cast<const float4*>(w1 + 4 * g);
    float4 b1q = *reinterpret_cast<const float4*>(b1 + 4 * g);
    float4 b2q = *reinterpret_cast<const float4*>(b2 + 4 * g);
    float w1v[4] = {w1q.x, w1q.y, w1q.z, w1q.w};
    float b1v[4] = {b1q.x, b1q.y, b1q.z, b1q.w};
    float b2v[4] = {b2q.x, b2q.y, b2q.z, b2q.w};

    // layer1 + relu (raw, pre-BN), packed pairs: h1[k][pp][j]
    u64 h1[2][2][4];
#pragma unroll
    for (int k = 0; k < 2; k++)
#pragma unroll
        for (int pp = 0; pp < 2; pp++)
#pragma unroll
            for (int j = 0; j < 4; j++) {
                u64 w1p = pk2(w1v[j], w1v[j]);
                u64 b1p = pk2(b1v[j], b1v[j]);
                h1[k][pp][j] = relu2(fma2(w1p, xp[k][pp], b1p));
            }

    // BN1 stats per column j, fold into layer2 weights
    float m1[4], inv1[4];
#pragma unroll
    for (int j = 0; j < 4; j++) {
        u64 s = add2(add2(h1[0][0][j], h1[0][1][j]), add2(h1[1][0][j], h1[1][1][j]));
        u64 q = mul2(h1[0][0][j], h1[0][0][j]);
        q = fma2(h1[0][1][j], h1[0][1][j], q);
        q = fma2(h1[1][0][j], h1[1][0][j], q);
        q = fma2(h1[1][1][j], h1[1][1][j], q);
        float sx, sy, qx, qy;
        upk2(s, sx, sy); upk2(q, qx, qy);
        float2 ss = warp_sum2(make_float2(sx + sy, qx + qy));
        float m = ss.x * (1.0f / BATCH);
        float var = fmaxf(ss.y * (1.0f / BATCH) - m * m, 0.0f);
        m1[j] = m;
        inv1[j] = rsqrtf(var + EPS);
    }

    // Folded layer2 weights as scalars (packed on the fly at use sites)
    float w2f[16], b2f[4];
    {
        float4 w2q0 = *reinterpret_cast<const float4*>(w2 + 16 * g);
        float4 w2q1 = *reinterpret_cast<const float4*>(w2 + 16 * g + 4);
        float4 w2q2 = *reinterpret_cast<const float4*>(w2 + 16 * g + 8);
        float4 w2q3 = *reinterpret_cast<const float4*>(w2 + 16 * g + 12);
        float w2v[16] = {w2q0.x, w2q0.y, w2q0.z, w2q0.w,
                         w2q1.x, w2q1.y, w2q1.z, w2q1.w,
                         w2q2.x, w2q2.y, w2q2.z, w2q2.w,
                         w2q3.x, w2q3.y, w2q3.z, w2q3.w};
#pragma unroll
        for (int i = 0; i < 4; i++) {
            float bb = b2v[i];
#pragma unroll
            for (int j = 0; j < 4; j++) {
                float wf = w2v[4 * i + j] * inv1[j];
                w2f[4 * i + j] = wf;
                bb -= wf * m1[j];
            }
            b2f[i] = bb;
        }
    }

    // layer2 + relu, packed: h2[k][pp][i]
    u64 h2[2][2][4];
#pragma unroll
    for (int k = 0; k < 2; k++)
#pragma unroll
        for (int pp = 0; pp < 2; pp++)
#pragma unroll
            for (int i = 0; i < 4; i++) {
                u64 acc = pk2(b2f[i], b2f[i]);
#pragma unroll
                for (int j = 0; j < 4; j++) {
                    u64 wp = pk2(w2f[4 * i + j], w2f[4 * i + j]);
                    acc = fma2(wp, h1[k][pp][j], acc);
                }
                h2[k][pp][i] = relu2(acc);
            }

    // BN2 per column i, normalize packed, transposed ST.64 half2 store
#pragma unroll
    for (int i = 0; i < 4; i++) {
        u64 s = add2(add2(h2[0][0][i], h2[0][1][i]), add2(h2[1][0][i], h2[1][1][i]));
        u64 q = mul2(h2[0][0][i], h2[0][0][i]);
        q = fma2(h2[0][1][i], h2[0][1][i], q);
        q = fma2(h2[1][0][i], h2[1][0][i], q);
        q = fma2(h2[1][1][i], h2[1][1][i], q);
        float sx, sy, qx, qy;
        upk2(s, sx, sy); upk2(q, qx, qy);
        float2 ss = warp_sum2(make_float2(sx + sy, qx + qy));
        float m = ss.x * (1.0f / BATCH);
        float var = fmaxf(ss.y * (1.0f / BATCH) - m * m, 0.0f);
        float inv = rsqrtf(var + EPS);

        u64 inv2 = pk2(inv, inv);
        u64 sh2  = pk2(-m * inv, -m * inv);
        __half2* dst = reinterpret_cast<__half2*>(&g_hT[(4 * g + i) * BATCH]);
#pragma unroll
        for (int k = 0; k < 2; k++) {
            u64 p0 = fma2(h2[k][0][i], inv2, sh2);
            u64 p1 = fma2(h2[k][1][i], inv2, sh2);
            float a0, a1, a2, a3;
            upk2(p0, a0, a1); upk2(p1, a2, a3);
            H22 hv;
            hv.a = __floats2half2_rn(a0, a1);
            hv.b = __floats2half2_rn(a2, a3);
            *reinterpret_cast<H22*>(&dst[64 * k + 2 * lane]) = hv;
        }
    }
}

// layer3 — EXACT R7 configuration (best measured 14.9us). One block (8 warps)
// per TF; warp handles 32 edges in 8 chunks of 4 staged LDG.128s; fp32 accum.
struct __align__(8) WC { float w; int boff; };

__device__ __forceinline__ void fma8(float* acc, float w, const uint4& v) {
    float2 f0 = __half22float2(*reinterpret_cast<const __half2*>(&v.x));
    float2 f1 = __half22float2(*reinterpret_cast<const __half2*>(&v.y));
    float2 f2 = __half22float2(*reinterpret_cast<const __half2*>(&v.z));
    float2 f3 = __half22float2(*reinterpret_cast<const __half2*>(&v.w));
    acc[0] = fmaf(w, f0.x, acc[0]);
    acc[1] = fmaf(w, f0.y, acc[1]);
    acc[2] = fmaf(w, f1.x, acc[2]);
    acc[3] = fmaf(w, f1.y, acc[3]);
    acc[4] = fmaf(w, f2.x, acc[4]);
    acc[5] = fmaf(w, f2.y, acc[5]);
    acc[6] = fmaf(w, f3.x, acc[6]);
    acc[7] = fmaf(w, f3.y, acc[7]);
}

__global__ __launch_bounds__(256) void k_layer3(
    const float* __restrict__ w3, const float* __restrict__ b3,
    const int* __restrict__ cols3,
    float* __restrict__ out)   // [BATCH, N_TF]
{
    const int tf = blockIdx.x;
    const int t = threadIdx.x;        // 0..255
    const int warp = t >> 5;
    const int lane = t & 31;

    __shared__ WC swc[EDGES3];
    __shared__ float sacc[8][BATCH];      // 8 KB
    __shared__ float2 sred[8];

    swc[t].w    = w3[tf * EDGES3 + t];
    swc[t].boff = cols3[tf * EDGES3 + t] * (BATCH * 2);   // bytes
    __syncthreads();

    const char* hbase = reinterpret_cast<const char*>(g_hT) + lane * 16;
    const int ebase = warp * 32;

    float acc[8];
#pragma unroll
    for (int s = 0; s < 8; s++) acc[s] = 0.f;

#pragma unroll
    for (int c = 0; c < 8; c++) {
        WC a0 = swc[ebase + 4 * c + 0];
        WC a1 = swc[ebase + 4 * c + 1];
        WC a2 = swc[ebase + 4 * c + 2];
        WC a3 = swc[ebase + 4 * c + 3];
        uint4 v0 = *reinterpret_cast<const uint4*>(hbase + a0.boff);
        uint4 v1 = *reinterpret_cast<const uint4*>(hbase + a1.boff);
        uint4 v2 = *reinterpret_cast<const uint4*>(hbase + a2.boff);
        uint4 v3 = *reinterpret_cast<const uint4*>(hbase + a3.boff);
        fma8(acc, a0.w, v0);
        fma8(acc, a1.w, v1);
        fma8(acc, a2.w, v2);
        fma8(acc, a3.w, v3);
    }

    // Park partials: warp's acc[s] is batch 8*lane+s
    *reinterpret_cast<float4*>(&sacc[warp][8 * lane])     = make_float4(acc[0], acc[1], acc[2], acc[3]);
    *reinterpret_cast<float4*>(&sacc[warp][8 * lane + 4]) = make_float4(acc[4], acc[5], acc[6], acc[7]);
    __syncthreads();

    // Thread t owns batch b = t: sum over the 8 warps' partials.
    float z = b3[tf];
#pragma unroll
    for (int w = 0; w < 8; w++) z += sacc[w][t];

    // Single-pass BN over the 256 batch values.
    float2 ss = warp_sum2(make_float2(z, z * z));
    if (lane == 0) sred[warp] = ss;
    __syncthreads();
    float S = 0.f, S2 = 0.f;
#pragma unroll
    for (int i = 0; i < 8; i++) { S += sred[i].x; S2 += sred[i].y; }
    float m = S * (1.0f / BATCH);
    float var = fmaxf(S2 * (1.0f / BATCH) - m * m, 0.0f);
    float inv = rsqrtf(var + EPS);

    out[t * N_TF + tf] = (z - m) * inv;
}

extern "C" void kernel_launch(void* const* d_in, const int* in_sizes, int n_in,
                              void* d_out, int out_size)
{
    const float* x  = (const float*)d_in[0];
    const float* w1 = (const float*)d_in[1];
    const float* b1 = (const float*)d_in[2];
    const float* w2 = (const float*)d_in[3];
    const float* b2 = (const float*)d_in[4];
    const float* w3 = (const float*)d_in[5];
    const float* b3 = (const float*)d_in[6];
    const int* cols3 = (const int*)d_in[12];
    float* out = (float*)d_out;

    k_layers12<<<N_GENES / GENES_PER_BLOCK, 256>>>(x, w1, b1, w2, b2);
    k_layer3<<<N_TF, 256>>>(w3, b3, cols3, out);
}